// round 8
// baseline (speedup 1.0000x reference)
#include <cuda_runtime.h>
#include <cuda_bf16.h>
#include <cstdint>

#define B_      1024
#define L_      50
#define K_      20
#define D_      64
#define NITEMS  100000
#define NUSERS  10000
#define ALPHA   0.2f

#define NT_PAD   12512              // n8-tiles padded to multiple of 16
#define NGROUPS  (NT_PAD / 16)      // 782 groups of 128 cols
#define STRIPS   8
#define SLOTS    18                 // 144 CTAs, one wave

__device__ float g_pu[B_ * D_];
// B fragments: [nt][j(4)][lane(32)] uint4 (k-step pair 2j,2j+1), column-paired
__device__ uint4 g_bfrag[NT_PAD * 4 * 32];     // 25.6 MB

__device__ __forceinline__ uint32_t f2tf32(float x) {
    uint32_t u;
    asm("cvt.rn.tf32.f32 %0, %1;" : "=r"(u) : "f"(x));
    return u;
}
__device__ __forceinline__ uint32_t smem_u32(const void* p) {
    uint32_t a;
    asm("{ .reg .u64 t; cvta.to.shared.u64 t, %1; cvt.u32.u64 %0, t; }"
        : "=r"(a) : "l"(p));
    return a;
}
__device__ __forceinline__ void cp_async16(uint32_t dst, const void* src) {
    asm volatile("cp.async.cg.shared.global [%0], [%1], 16;"
                 :: "r"(dst), "l"(src) : "memory");
}
#define CP_COMMIT() asm volatile("cp.async.commit_group;" ::: "memory")
#define CP_WAIT(n)  asm volatile("cp.async.wait_group %0;" :: "n"(n) : "memory")

__device__ __forceinline__ void mma_tf32(float& c0, float& c1, float& c2, float& c3,
                                         uint32_t a0, uint32_t a1, uint32_t a2, uint32_t a3,
                                         uint32_t b0, uint32_t b1) {
    asm volatile("mma.sync.aligned.m16n8k8.row.col.f32.tf32.tf32.f32 "
                 "{%0,%1,%2,%3}, {%4,%5,%6,%7}, {%8,%9}, {%0,%1,%2,%3};"
                 : "+f"(c0), "+f"(c1), "+f"(c2), "+f"(c3)
                 : "r"(a0), "r"(a1), "r"(a2), "r"(a3), "r"(b0), "r"(b1));
}

__device__ __forceinline__ float tree_sum20(const float* s) {
    float t1[10];
#pragma unroll
    for (int i = 0; i < 10; i++) t1[i] = s[2 * i] + s[2 * i + 1];
    float t2[5];
#pragma unroll
    for (int i = 0; i < 5; i++) t2[i] = t1[2 * i] + t1[2 * i + 1];
    return ((t2[0] + t2[1]) + (t2[2] + t2[3])) + t2[4];
}

// ===========================================================================
// Fused prep kernel (256 threads/block):
//   blocks [0,128):  recurrence for 8 batch rows -> g_pu
//   blocks [128,..): B fragment transform, smem-staged (vectorized LDG)
// ===========================================================================
#define RECUR_BLOCKS 128
#define BFRAG_BLOCKS (NT_PAD / 2)           // 6256, one block per 16 item rows

__global__ void __launch_bounds__(256)
prep_kernel(const float* __restrict__ item,
            const float* __restrict__ user,
            const float* __restrict__ mem_init,
            const int*   __restrict__ user_id,
            const int*   __restrict__ seq,
            const int*   __restrict__ seq_len)
{
    __shared__ float sstage[16 * 68];       // 16 rows x 64 floats, padded (+4)
    __shared__ int   sseq[8 * L_];
    const int tid = threadIdx.x;

    if (blockIdx.x >= RECUR_BLOCKS) {
        // ------- B fragment transform: 16 item rows -> 256 uint4 -------
        const int ntg = blockIdx.x - RECUR_BLOCKS;        // 16-row group
        {
            int row = tid >> 4;               // 0..15
            int f4  = tid & 15;               // float4 within row
            int n   = ntg * 16 + row;
            float4 v = make_float4(0.f, 0.f, 0.f, 0.f);
            if (n < NITEMS)
                v = *((const float4*)(item + (size_t)n * 64) + f4);
            *(float4*)&sstage[row * 68 + f4 * 4] = v;
        }
        __syncthreads();

        const int lane = tid & 31;
        const int j    = (tid >> 5) & 3;
        const int par  = tid >> 7;            // nt_local (0/1)
        const int w    = lane >> 2;
        const int t    = lane & 3;
        // column-pair permutation within the 16-row group
        const int nl = (w & 1) ? (2 * w - 1 + 2 * par) : (2 * w + 2 * par);
        uint4 v;
        v.x = f2tf32(sstage[nl * 68 + (j * 4 + 0) * 4 + t]);
        v.y = f2tf32(sstage[nl * 68 + (j * 4 + 1) * 4 + t]);
        v.z = f2tf32(sstage[nl * 68 + (j * 4 + 2) * 4 + t]);
        v.w = f2tf32(sstage[nl * 68 + (j * 4 + 3) * 4 + t]);
        g_bfrag[(size_t)ntg * 256 + tid] = v;
        return;
    }

    // ---------------- recurrence: 8 warps = 8 batch rows ----------------
    const int wid  = tid >> 5;
    const int lane = tid & 31;
    const int b    = blockIdx.x * 8 + wid;

    for (int i = tid; i < 8 * L_; i += 256)
        sseq[i] = seq[blockIdx.x * 8 * L_ + i];
    __syncthreads();

    float m0[K_], m1[K_];
    const float* mi = mem_init + (size_t)b * K_ * D_;
#pragma unroll
    for (int k = 0; k < K_; k++) {
        m0[k] = mi[k * D_ + lane];
        m1[k] = mi[k * D_ + lane + 32];
    }

    const int T = seq_len[b];
    const int* sq = sseq + wid * L_;

    for (int t0 = 0; t0 < T; t0 += 8) {
        int nt = min(8, T - t0);
        float e0[8], e1[8];
#pragma unroll
        for (int i = 0; i < 8; i++) {
            if (i < nt) {
                int idx = sq[t0 + i];
                e0[i] = __ldg(item + (size_t)idx * D_ + lane);
                e1[i] = __ldg(item + (size_t)idx * D_ + lane + 32);
            }
        }
#pragma unroll
        for (int i = 0; i < 8; i++) {
            if (i >= nt) break;
            float s[K_];
#pragma unroll
            for (int k = 0; k < K_; k++) {
                float p = fmaf(m0[k], e0[i], m1[k] * e1[i]);
#pragma unroll
                for (int off = 16; off > 0; off >>= 1)
                    p += __shfl_xor_sync(0xffffffffu, p, off);
                s[k] = p;
            }
#pragma unroll
            for (int k = 0; k < K_; k++) s[k] = __expf(s[k]);
            float inv = __fdividef(1.f, tree_sum20(s));
            float er0 = __fdividef(1.f, 1.f + __expf(-e0[i]));
            float er1 = __fdividef(1.f, 1.f + __expf(-e1[i]));
            float ex0 = __expf(2.f * e0[i]);
            float ex1 = __expf(2.f * e1[i]);
            float ad0 = __fdividef(ex0 - 1.f, ex0 + 1.f);
            float ad1 = __fdividef(ex1 - 1.f, ex1 + 1.f);
#pragma unroll
            for (int k = 0; k < K_; k++) {
                float z = s[k] * inv;
                m0[k] = m0[k] * (1.f - z * er0) + z * ad0;
                m1[k] = m1[k] * (1.f - z * er1) + z * ad1;
            }
        }
    }

    int lidx = sq[L_ - 1];
    float l0 = __ldg(item + (size_t)lidx * D_ + lane);
    float l1 = __ldg(item + (size_t)lidx * D_ + lane + 32);

    float s[K_];
#pragma unroll
    for (int k = 0; k < K_; k++) {
        float p = fmaf(m0[k], l0, m1[k] * l1);
#pragma unroll
        for (int off = 16; off > 0; off >>= 1)
            p += __shfl_xor_sync(0xffffffffu, p, off);
        s[k] = __expf(p);
    }
    float inv = __fdividef(1.f, tree_sum20(s));

    float p0 = 0.f, p1 = 0.f;
#pragma unroll
    for (int k = 0; k < K_; k++) {
        float z = s[k] * inv;
        p0 = fmaf(z, m0[k], p0);
        p1 = fmaf(z, m1[k], p1);
    }

    int uid = user_id[b];
    g_pu[b * D_ + lane]      = user[(size_t)uid * D_ + lane]      + ALPHA * p0;
    g_pu[b * D_ + lane + 32] = user[(size_t)uid * D_ + lane + 32] + ALPHA * p1;
}

// ===========================================================================
// Persistent GEMM: 144 CTAs (8 strips x 18 slots), 512 thr = 16 warps (4Mx4N).
// A strip (128x64) in smem fragment layout; B: 3-stage cp.async ring.
// Previous iteration's stores interleaved into current j-loop (under MMA).
// ===========================================================================
#define TILE_U4   2048                       // uint4 per 128-col B group
#define SMEM_A_U4 2048                       // 32 KB A stage
#define GEMM_SMEM_BYTES ((SMEM_A_U4 + 3 * TILE_U4) * 16)   // 128 KB

__global__ void __launch_bounds__(512, 1)
gemm_persist(float* __restrict__ C)
{
    extern __shared__ uint4 smem[];
    uint4* const sA = smem;                  // [2048]
    uint4* const sB = smem + SMEM_A_U4;      // [3][2048]
    const uint32_t sBb = smem_u32(sB);

    const int tid  = threadIdx.x;
    const int wid  = tid >> 5;
    const int lane = tid & 31;
    const int wm   = wid >> 2;               // 0..3 (32 rows)
    const int wn   = wid & 3;                // 0..3 (32 cols)
    const int g    = lane >> 2;
    const int t    = lane & 3;

    const int strip = blockIdx.x & 7;
    const int slot  = blockIdx.x >> 3;

    // ---- stage A strip into smem fragment layout ----
    {
        const float* pu = g_pu + (size_t)strip * 128 * 64;
#pragma unroll
        for (int u = tid; u < SMEM_A_U4; u += 512) {
            int ln = u & 31;
            int ks = (u >> 5) & 7;
            int mt = u >> 8;
            int row = mt * 16 + (ln >> 2);
            int k0  = ks * 8 + (ln & 3);
            uint4 v;
            v.x = f2tf32(pu[row * 64 + k0]);
            v.y = f2tf32(pu[(row + 8) * 64 + k0]);
            v.z = f2tf32(pu[row * 64 + k0 + 4]);
            v.w = f2tf32(pu[(row + 8) * 64 + k0 + 4]);
            sA[u] = v;
        }
    }

    const int row_base = strip * 128 + wm * 32;

    // ---- prologue: stage groups for iter 0,1 ----
#pragma unroll
    for (int pf = 0; pf < 2; pf++) {
        int grp = slot + pf * SLOTS;
        if (grp < NGROUPS) {
            const uint4* src = g_bfrag + (size_t)grp * TILE_U4 + tid;
            uint32_t dst = sBb + (uint32_t)(pf * TILE_U4 + tid) * 16u;
#pragma unroll
            for (int r = 0; r < 4; r++)
                cp_async16(dst + r * 512 * 16, src + r * 512);
        }
        CP_COMMIT();
    }

    float accp[2][2][2][4];                  // previous iteration's results
    int prev_grp = -1;

    int iter = 0;
    for (int grp = slot; grp < NGROUPS; grp += SLOTS, iter++) {
        const int buf = iter - (iter / 3) * 3;
        CP_WAIT(1);
        __syncthreads();

        // prefetch iter+2
        {
            int nxt = grp + 2 * SLOTS;
            if (nxt < NGROUPS) {
                const int pbuf = (buf + 2 >= 3) ? buf - 1 : buf + 2;
                const uint4* src = g_bfrag + (size_t)nxt * TILE_U4 + tid;
                uint32_t dst = sBb + (uint32_t)(pbuf * TILE_U4 + tid) * 16u;
#pragma unroll
                for (int r = 0; r < 4; r++)
                    cp_async16(dst + r * 512 * 16, src + r * 512);
            }
            CP_COMMIT();
        }

        float acc[2][2][2][4];
#pragma unroll
        for (int i = 0; i < 2; i++)
#pragma unroll
            for (int p = 0; p < 2; p++)
#pragma unroll
                for (int q = 0; q < 2; q++)
#pragma unroll
                    for (int r = 0; r < 4; r++) acc[i][p][q][r] = 0.f;

        const uint4* Bs = sB + buf * TILE_U4;
#pragma unroll
        for (int j = 0; j < 4; j++) {
            uint4 b[2][2];
#pragma unroll
            for (int p = 0; p < 2; p++)
#pragma unroll
                for (int q = 0; q < 2; q++)
                    b[p][q] = Bs[((wn * 4 + p * 2 + q) * 4 + j) * 32 + lane];
            uint4 a[2][2];
#pragma unroll
            for (int mi = 0; mi < 2; mi++)
#pragma unroll
                for (int s = 0; s < 2; s++)
                    a[mi][s] = sA[((wm * 2 + mi) * 8 + 2 * j + s) * 32 + lane];
#pragma unroll
            for (int s = 0; s < 2; s++)
#pragma unroll
                for (int mi = 0; mi < 2; mi++)
#pragma unroll
                    for (int p = 0; p < 2; p++)
#pragma unroll
                        for (int q = 0; q < 2; q++) {
                            uint32_t b0 = (s == 0) ? b[p][q].x : b[p][q].z;
                            uint32_t b1 = (s == 0) ? b[p][q].y : b[p][q].w;
                            mma_tf32(acc[mi][p][q][0], acc[mi][p][q][1],
                                     acc[mi][p][q][2], acc[mi][p][q][3],
                                     a[mi][s].x, a[mi][s].y, a[mi][s].z, a[mi][s].w,
                                     b0, b1);
                        }

            // interleaved store of PREVIOUS iteration: pair (mi,p) = j
            if (prev_grp >= 0) {
                const int mi = j >> 1;
                const int p  = j & 1;
                int base16 = prev_grp * 128 + wn * 32 + p * 16;
                if (base16 < NITEMS) {            // NITEMS % 16 == 0
                    int row0 = row_base + mi * 16 + g;
                    int col  = base16 + 4 * t;
                    __stcs((float4*)(C + (size_t)row0 * NITEMS + col),
                           make_float4(accp[mi][p][0][0], accp[mi][p][0][1],
                                       accp[mi][p][1][0], accp[mi][p][1][1]));
                    __stcs((float4*)(C + (size_t)(row0 + 8) * NITEMS + col),
                           make_float4(accp[mi][p][0][2], accp[mi][p][0][3],
                                       accp[mi][p][1][2], accp[mi][p][1][3]));
                }
            }
        }

        // retire: acc -> accp
#pragma unroll
        for (int i = 0; i < 2; i++)
#pragma unroll
            for (int p = 0; p < 2; p++)
#pragma unroll
                for (int q = 0; q < 2; q++)
#pragma unroll
                    for (int r = 0; r < 4; r++) accp[i][p][q][r] = acc[i][p][q][r];
        prev_grp = grp;
    }

    // tail: store final iteration's results
    if (prev_grp >= 0) {
#pragma unroll
        for (int mi = 0; mi < 2; mi++) {
            int row0 = row_base + mi * 16 + g;
#pragma unroll
            for (int p = 0; p < 2; p++) {
                int base16 = prev_grp * 128 + wn * 32 + p * 16;
                if (base16 < NITEMS) {
                    int col = base16 + 4 * t;
                    __stcs((float4*)(C + (size_t)row0 * NITEMS + col),
                           make_float4(accp[mi][p][0][0], accp[mi][p][0][1],
                                       accp[mi][p][1][0], accp[mi][p][1][1]));
                    __stcs((float4*)(C + (size_t)(row0 + 8) * NITEMS + col),
                           make_float4(accp[mi][p][0][2], accp[mi][p][0][3],
                                       accp[mi][p][1][2], accp[mi][p][1][3]));
                }
            }
        }
    }
}

// ===========================================================================
extern "C" void kernel_launch(void* const* d_in, const int* in_sizes, int n_in,
                              void* d_out, int out_size)
{
    const float* item_table  = (const float*)d_in[0];
    const float* user_table  = (const float*)d_in[1];
    const float* memory_init = (const float*)d_in[2];
    const int*   user_id     = (const int*)d_in[3];
    const int*   seq         = (const int*)d_in[4];
    const int*   seq_length  = (const int*)d_in[5];
    float*       scores      = (float*)d_out;

    cudaFuncSetAttribute(gemm_persist,
                         cudaFuncAttributeMaxDynamicSharedMemorySize,
                         GEMM_SMEM_BYTES);

    prep_kernel<<<RECUR_BLOCKS + BFRAG_BLOCKS, 256>>>(
        item_table, user_table, memory_init, user_id, seq, seq_length);

    gemm_persist<<<STRIPS * SLOTS, 512, GEMM_SMEM_BYTES>>>(scores);
}